// round 10
// baseline (speedup 1.0000x reference)
#include <cuda_runtime.h>
#include <cuda_bf16.h>
#include <cstdint>

#define B_  8
#define NK_ 2048
#define NQ_ 2048
#define D_  256
#define H_  1024
#define KS3 768     // 3*256: split-K for D-dim GEMMs

// ======================= low-level helpers =======================
__device__ __forceinline__ uint32_t smem_u32(const void* p) {
    uint32_t a;
    asm("{ .reg .u64 t; cvta.to.shared.u64 t, %1; cvt.u32.u64 %0, t; }" : "=r"(a) : "l"(p));
    return a;
}
#define CP16(sm, g) asm volatile("cp.async.cg.shared.global [%0], [%1], 16;" :: "r"(sm), "l"(g))
#define CP_COMMIT   asm volatile("cp.async.commit_group;" ::: "memory")
#define CP_WAIT0    asm volatile("cp.async.wait_group 0;" ::: "memory")

__device__ __forceinline__ void ldm_x4(uint32_t* r, uint32_t addr) {
    asm volatile("ldmatrix.sync.aligned.m8n8.x4.shared.b16 {%0,%1,%2,%3}, [%4];"
                 : "=r"(r[0]), "=r"(r[1]), "=r"(r[2]), "=r"(r[3]) : "r"(addr));
}
__device__ __forceinline__ void mma16816(float* c, const uint32_t* a, const uint32_t* b) {
    asm volatile("mma.sync.aligned.m16n8k16.row.col.f32.bf16.bf16.f32 "
                 "{%0,%1,%2,%3}, {%4,%5,%6,%7}, {%8,%9}, {%0,%1,%2,%3};"
                 : "+f"(c[0]), "+f"(c[1]), "+f"(c[2]), "+f"(c[3])
                 : "r"(a[0]), "r"(a[1]), "r"(a[2]), "r"(a[3]), "r"(b[0]), "r"(b[1]));
}

// ======================= scratch =======================
__device__ __align__(128) __nv_bfloat16 g_K2 [(size_t)B_*NK_*KS3];   // KEY   A-form [hi|lo|hi]
__device__ __align__(128) __nv_bfloat16 g_V2 [(size_t)B_*NK_*KS3];   // VALUE A-form
__device__ __align__(128) __nv_bfloat16 g_Q2 [(size_t)B_*NQ_*KS3];   // QUERY B-form [hi|hi|lo]
__device__ __align__(128) __nv_bfloat16 g_P2 [(size_t)B_*NK_*KS3];   // P     A-form
__device__ __align__(128) float g_St[(size_t)B_*NQ_*NK_];            // S'^T  [b][k][i] fp32
__device__ __align__(128) float g_Z [(size_t)B_*NK_*D_];             // Z fp32 [i,d]
__device__ __align__(128) __nv_bfloat16 g_Zth[(size_t)B_*D_*NK_];    // Z^T hi [d][i]
__device__ __align__(128) __nv_bfloat16 g_Ztl[(size_t)B_*D_*NK_];    // Z^T lo [d][i]
__device__ __align__(128) float g_tstat[(size_t)B_*16*NK_*2];        // per-tile (max,sum)
__device__ __align__(128) __nv_bfloat16 g_Gt2[D_*KS3];               // B-form
__device__ __align__(128) __nv_bfloat16 g_M22[D_*KS3];               // B-form
__device__ float g_Gt[D_*D_];
__device__ float g_M2[D_*D_];
__device__ float g_linT[H_*D_];
__device__ float g_gv[D_];
__device__ float g_cv[D_];
__device__ float g_v [B_*NQ_];
__device__ float g_m [B_*NK_];
__device__ float g_si[B_*NK_];

// ======================= tiny precompute =======================
__global__ void transpose_lin(const float* __restrict__ lin_w) {
    int idx = blockIdx.x * 256 + threadIdx.x;
    int h = idx >> 8, d = idx & 255;
    g_linT[h * D_ + d] = lin_w[d * H_ + h];
}
__global__ void vec_pre(const float* __restrict__ Wk_b, const float* __restrict__ Wq_w,
                        const float* __restrict__ lin_w, const float* __restrict__ Wv_b) {
    int t = threadIdx.x;
    if (blockIdx.x == 0) {
        float s = 0.f;
        for (int h = 0; h < H_; ++h) s += Wk_b[h] * Wq_w[h * D_ + t];
        g_gv[t] = s;
    } else {
        float s = 0.f;
        for (int h = 0; h < H_; ++h) s += lin_w[t * H_ + h] * Wv_b[h];
        g_cv[t] = s;
    }
}
__global__ void small_gemm_tn(const float* __restrict__ Wq_w,
                              const float* __restrict__ Wk_w,
                              const float* __restrict__ Wv_w) {
    const float *A, *Bm; float* C;
    if (blockIdx.z == 0) { A = Wq_w;   Bm = Wk_w; C = g_Gt; }
    else                 { A = g_linT; Bm = Wv_w; C = g_M2; }
    __shared__ float As[16][33], Bs[16][33];
    int tid = threadIdx.x, tx = tid & 15, ty = tid >> 4;
    int m0 = blockIdx.x * 32, n0 = blockIdx.y * 32;
    float acc[2][2] = {};
    for (int k0 = 0; k0 < H_; k0 += 16) {
        #pragma unroll
        for (int p = 0; p < 2; ++p) {
            int e = tid + p * 256; int kk = e >> 5, mm = e & 31;
            As[kk][mm] = A [(k0 + kk) * D_ + m0 + mm];
            Bs[kk][mm] = Bm[(k0 + kk) * D_ + n0 + mm];
        }
        __syncthreads();
        #pragma unroll
        for (int kk = 0; kk < 16; ++kk) {
            float a0 = As[kk][ty*2], a1 = As[kk][ty*2+1];
            float b0 = Bs[kk][tx*2], b1 = Bs[kk][tx*2+1];
            acc[0][0] += a0*b0; acc[0][1] += a0*b1;
            acc[1][0] += a1*b0; acc[1][1] += a1*b1;
        }
        __syncthreads();
    }
    #pragma unroll
    for (int i = 0; i < 2; ++i)
        #pragma unroll
        for (int j = 0; j < 2; ++j)
            C[(m0 + ty*2 + i) * D_ + n0 + tx*2 + j] = acc[i][j];
}
__global__ void qdotg(const float* __restrict__ Q) {
    int gw   = (blockIdx.x * blockDim.x + threadIdx.x) >> 5;
    int lane = threadIdx.x & 31;
    const float* q = Q + (size_t)gw * D_;
    float s = 0.f;
    for (int t = lane; t < D_; t += 32) s += q[t] * g_gv[t];
    #pragma unroll
    for (int o = 16; o; o >>= 1) s += __shfl_xor_sync(0xffffffffu, s, o);
    if (!lane) g_v[gw] = s;
}

// fp32 [rows,256] -> 3-block split [rows,768].  AFORM: [hi|lo|hi]  else [hi|hi|lo]
template<bool AFORM>
__global__ void split_rows(const float* __restrict__ X, __nv_bfloat16* __restrict__ Y) {
    size_t idx = (size_t)blockIdx.x * 256 + threadIdx.x;
    size_t row = idx >> 8; int c = (int)(idx & 255);
    float x = X[idx];
    __nv_bfloat16 hi = __float2bfloat16(x);
    __nv_bfloat16 lo = __float2bfloat16(x - __bfloat162float(hi));
    __nv_bfloat16* r = Y + row * KS3 + c;
    r[0] = hi;
    if (AFORM) { r[256] = lo; r[512] = hi; }
    else       { r[256] = hi; r[512] = lo; }
}

// ======================= HMMA GEMM (for P and Z) =======================
// EPI 0: fp32 store (+opt bias[col]), ldc given.
// EPI 2: 3-block A-form split store.
template<int EPI>
__global__ __launch_bounds__(256, 2)
void mma_gemm(const __nv_bfloat16* __restrict__ A, const __nv_bfloat16* __restrict__ Bm,
              void* __restrict__ dst, const float* __restrict__ bias,
              int Ktot, size_t sA, size_t sB, size_t sD, int ldc)
{
    __shared__ __align__(16) char smA[2][128 * 80];
    __shared__ __align__(16) char smB[2][128 * 80];
    int tid = threadIdx.x, wid = tid >> 5, lane = tid & 31;
    int b = blockIdx.z;
    int m0 = blockIdx.x * 128, n0 = blockIdx.y * 128;
    A  += (size_t)b * sA;
    Bm += (size_t)b * sB;
    const int wm = wid & 1, wn = wid >> 1;
    float acc[4][4][4] = {};

    auto issue = [&](int c, int buf) {
        #pragma unroll
        for (int it = 0; it < 2; ++it) {
            int e = tid + it * 256;
            int r = e >> 2, q = e & 3;
            CP16(smem_u32(&smA[buf][r * 80 + q * 16]), A  + (size_t)(m0 + r) * Ktot + c * 32 + q * 8);
            CP16(smem_u32(&smB[buf][r * 80 + q * 16]), Bm + (size_t)(n0 + r) * Ktot + c * 32 + q * 8);
        }
    };

    const int nc = Ktot >> 5;
    issue(0, 0); CP_COMMIT;
    int buf = 0;
    for (int c = 0; c < nc; ++c) {
        CP_WAIT0;
        __syncthreads();
        if (c + 1 < nc) { issue(c + 1, buf ^ 1); CP_COMMIT; }
        #pragma unroll
        for (int ks = 0; ks < 2; ++ks) {
            uint32_t a[4][4], bb[4][2];
            #pragma unroll
            for (int t = 0; t < 4; ++t) {
                uint32_t addr = smem_u32(&smA[buf][(wm * 64 + t * 16 + (lane & 15)) * 80
                                                   + ks * 32 + ((lane >> 4) << 4)]);
                ldm_x4(a[t], addr);
            }
            #pragma unroll
            for (int u2 = 0; u2 < 2; ++u2) {
                uint32_t row = wn * 32 + u2 * 16 + ((lane >> 4) << 3) + (lane & 7);
                uint32_t koff = ks * 32 + (((lane >> 3) & 1) << 4);
                uint32_t r4[4];
                ldm_x4(r4, smem_u32(&smB[buf][row * 80 + koff]));
                bb[u2*2][0] = r4[0]; bb[u2*2][1] = r4[1];
                bb[u2*2+1][0] = r4[2]; bb[u2*2+1][1] = r4[3];
            }
            #pragma unroll
            for (int t = 0; t < 4; ++t)
                #pragma unroll
                for (int u = 0; u < 4; ++u)
                    mma16816(acc[t][u], a[t], bb[u]);
        }
        buf ^= 1;
    }

    #pragma unroll
    for (int t = 0; t < 4; ++t) {
        int r0 = m0 + wm * 64 + t * 16 + (lane >> 2);
        #pragma unroll
        for (int u = 0; u < 4; ++u) {
            int cc = n0 + wn * 32 + u * 8 + (lane & 3) * 2;
            float x0 = acc[t][u][0], x1 = acc[t][u][1];
            float x2 = acc[t][u][2], x3 = acc[t][u][3];
            if (EPI == 0) {
                float* C = (float*)dst + (size_t)b * sD;
                float b0 = bias ? bias[cc] : 0.f, b1 = bias ? bias[cc + 1] : 0.f;
                float2 v0 = {x0 + b0, x1 + b1};
                float2 v1 = {x2 + b0, x3 + b1};
                *(float2*)&C[(size_t)r0 * ldc + cc]       = v0;
                *(float2*)&C[(size_t)(r0 + 8) * ldc + cc] = v1;
            } else {
                __nv_bfloat16* Y = (__nv_bfloat16*)dst + (size_t)b * sD;
                #pragma unroll
                for (int h = 0; h < 2; ++h) {
                    int row = r0 + h * 8;
                    float y0 = h ? x2 : x0, y1 = h ? x3 : x1;
                    __nv_bfloat16 h0 = __float2bfloat16(y0);
                    __nv_bfloat16 h1 = __float2bfloat16(y1);
                    __nv_bfloat16 l0 = __float2bfloat16(y0 - __bfloat162float(h0));
                    __nv_bfloat16 l1 = __float2bfloat16(y1 - __bfloat162float(h1));
                    __nv_bfloat162 hp; hp.x = h0; hp.y = h1;
                    __nv_bfloat162 lp; lp.x = l0; lp.y = l1;
                    *(__nv_bfloat162*)&Y[(size_t)row * KS3 + cc]       = hp;
                    *(__nv_bfloat162*)&Y[(size_t)row * KS3 + 256 + cc] = lp;
                    *(__nv_bfloat162*)&Y[(size_t)row * KS3 + 512 + cc] = hp;
                }
            }
        }
    }
}

// ============ S-GEMM with fused (v,scale), tile-stats, transposed store ============
// C[i,k] tile = P2[i,:]·Q2[k,:]^T ; x=(C+v_k)*scale ; per-row tile (max,Σexp) -> g_tstat ;
// x stored transposed to g_St[k][i].
__global__ __launch_bounds__(256, 2)
void sgemm_stats()
{
    __shared__ __align__(16) char SM[40960];
    char* smAb = SM; char* smBb = SM + 20480;
    int tid = threadIdx.x, wid = tid >> 5, lane = tid & 31;
    int b = blockIdx.z;
    int m0 = blockIdx.x * 128, n0 = blockIdx.y * 128;   // m=i, n=k
    const __nv_bfloat16* A  = g_P2 + (size_t)b * NK_ * KS3;
    const __nv_bfloat16* Bm = g_Q2 + (size_t)b * NQ_ * KS3;
    const int wm = wid & 1, wn = wid >> 1;
    float acc[4][4][4] = {};

    auto issue = [&](int c, int buf) {
        #pragma unroll
        for (int it = 0; it < 2; ++it) {
            int e = tid + it * 256;
            int r = e >> 2, q = e & 3;
            CP16(smem_u32(smAb + buf * 10240 + r * 80 + q * 16), A  + (size_t)(m0 + r) * KS3 + c * 32 + q * 8);
            CP16(smem_u32(smBb + buf * 10240 + r * 80 + q * 16), Bm + (size_t)(n0 + r) * KS3 + c * 32 + q * 8);
        }
    };

    issue(0, 0); CP_COMMIT;
    int buf = 0;
    for (int c = 0; c < 24; ++c) {
        CP_WAIT0;
        __syncthreads();
        if (c + 1 < 24) { issue(c + 1, buf ^ 1); CP_COMMIT; }
        #pragma unroll
        for (int ks = 0; ks < 2; ++ks) {
            uint32_t a[4][4], bb[4][2];
            #pragma unroll
            for (int t = 0; t < 4; ++t)
                ldm_x4(a[t], smem_u32(smAb + buf * 10240
                       + (wm * 64 + t * 16 + (lane & 15)) * 80 + ks * 32 + ((lane >> 4) << 4)));
            #pragma unroll
            for (int u2 = 0; u2 < 2; ++u2) {
                uint32_t row = wn * 32 + u2 * 16 + ((lane >> 4) << 3) + (lane & 7);
                uint32_t koff = ks * 32 + (((lane >> 3) & 1) << 4);
                uint32_t r4[4];
                ldm_x4(r4, smem_u32(smBb + buf * 10240 + row * 80 + koff));
                bb[u2*2][0] = r4[0]; bb[u2*2][1] = r4[1];
                bb[u2*2+1][0] = r4[2]; bb[u2*2+1][1] = r4[3];
            }
            #pragma unroll
            for (int t = 0; t < 4; ++t)
                #pragma unroll
                for (int u = 0; u < 4; ++u)
                    mma16816(acc[t][u], a[t], bb[u]);
        }
        buf ^= 1;
    }
    __syncthreads();   // smem reuse below

    // x = (acc + v[col]) * scale
    const float scale = 0.03125f;
    const float* vb = g_v + b * NQ_;
    float vc0[4], vc1[4];
    #pragma unroll
    for (int u = 0; u < 4; ++u) {
        int cc = n0 + wn * 32 + u * 8 + (lane & 3) * 2;
        vc0[u] = vb[cc]; vc1[u] = vb[cc + 1];
    }
    #pragma unroll
    for (int t = 0; t < 4; ++t)
        #pragma unroll
        for (int u = 0; u < 4; ++u) {
            acc[t][u][0] = (acc[t][u][0] + vc0[u]) * scale;
            acc[t][u][1] = (acc[t][u][1] + vc1[u]) * scale;
            acc[t][u][2] = (acc[t][u][2] + vc0[u]) * scale;
            acc[t][u][3] = (acc[t][u][3] + vc1[u]) * scale;
        }

    float* sred  = (float*)SM;            // [128][4]
    float* sred2 = (float*)SM + 512;      // [128][4]
    float* stg   = (float*)SM + 1024 + wid * 1056;   // 32x33 per warp

    // per-row max over this tile's 128 cols
    #pragma unroll
    for (int t = 0; t < 4; ++t)
        #pragma unroll
        for (int h = 0; h < 2; ++h) {
            float mx = -1e30f;
            #pragma unroll
            for (int u = 0; u < 4; ++u)
                mx = fmaxf(mx, fmaxf(acc[t][u][h*2], acc[t][u][h*2+1]));
            mx = fmaxf(mx, __shfl_xor_sync(0xffffffffu, mx, 1));
            mx = fmaxf(mx, __shfl_xor_sync(0xffffffffu, mx, 2));
            if ((lane & 3) == 0)
                sred[(wm*64 + t*16 + (lane>>2) + h*8) * 4 + wn] = mx;
        }
    __syncthreads();
    #pragma unroll
    for (int t = 0; t < 4; ++t)
        #pragma unroll
        for (int h = 0; h < 2; ++h) {
            int rl = wm*64 + t*16 + (lane>>2) + h*8;
            float M = fmaxf(fmaxf(sred[rl*4], sred[rl*4+1]), fmaxf(sred[rl*4+2], sred[rl*4+3]));
            float s = 0.f;
            #pragma unroll
            for (int u = 0; u < 4; ++u)
                s += __expf(acc[t][u][h*2] - M) + __expf(acc[t][u][h*2+1] - M);
            s += __shfl_xor_sync(0xffffffffu, s, 1);
            s += __shfl_xor_sync(0xffffffffu, s, 2);
            if ((lane & 3) == 0) sred2[rl*4 + wn] = s;
        }
    __syncthreads();
    if (wid < 2) {   // wn==0 warps; wm == wid
        #pragma unroll
        for (int hh = 0; hh < 2; ++hh) {
            int rl = wid*64 + hh*32 + lane;
            float M = fmaxf(fmaxf(sred[rl*4], sred[rl*4+1]), fmaxf(sred[rl*4+2], sred[rl*4+3]));
            float S = sred2[rl*4] + sred2[rl*4+1] + sred2[rl*4+2] + sred2[rl*4+3];
            size_t o = (((size_t)b*16 + blockIdx.y) * NK_ + m0 + rl) * 2;
            g_tstat[o] = M; g_tstat[o+1] = S;
        }
    }

    // transposed store: g_St[k][i]
    float* Stb = g_St + (size_t)b * NQ_ * NK_;
    #pragma unroll
    for (int h2 = 0; h2 < 2; ++h2) {
        #pragma unroll
        for (int tt = 0; tt < 2; ++tt) {
            int t = h2*2 + tt;
            #pragma unroll
            for (int u = 0; u < 4; ++u) {
                int col = u*8 + (lane&3)*2;
                int rw = tt*16 + (lane>>2);
                stg[rw*33 + col]     = acc[t][u][0];
                stg[rw*33 + col + 1] = acc[t][u][1];
                stg[(rw+8)*33 + col]     = acc[t][u][2];
                stg[(rw+8)*33 + col + 1] = acc[t][u][3];
            }
        }
        __syncwarp();
        int krow = n0 + wn*32 + lane;
        float* drow = Stb + (size_t)krow * NK_ + m0 + wm*64 + h2*32;
        #pragma unroll
        for (int q = 0; q < 8; ++q) {
            float4 vv = { stg[(q*4+0)*33 + lane], stg[(q*4+1)*33 + lane],
                          stg[(q*4+2)*33 + lane], stg[(q*4+3)*33 + lane] };
            *(float4*)(drow + q*4) = vv;
        }
        __syncwarp();
    }
}

// combine 16 tile-stats -> m_i, 1/sum
__global__ void stats_combine() {
    int b = blockIdx.y;
    int i = blockIdx.x * 256 + threadIdx.x;
    float pm[16], ps[16];
    float m = -1e30f;
    #pragma unroll
    for (int j = 0; j < 16; ++j) {
        size_t o = (((size_t)b*16 + j) * NK_ + i) * 2;
        pm[j] = g_tstat[o]; ps[j] = g_tstat[o+1];
        m = fmaxf(m, pm[j]);
    }
    float s = 0.f;
    #pragma unroll
    for (int j = 0; j < 16; ++j) s += ps[j] * __expf(pm[j] - m);
    g_m [b*NK_ + i] = m;
    g_si[b*NK_ + i] = 1.0f / s;
}

// Z fp32 [i,d] -> Zth[d][i] hi, Ztl[d][i] lo
__global__ void transpose_split_z() {
    __shared__ float sm[32][33];
    int b = blockIdx.z;
    int i0 = blockIdx.x * 32, d0 = blockIdx.y * 32;
    int tx = threadIdx.x, ty = threadIdx.y;
    const float* Z = g_Z + (size_t)b * NK_ * D_;
    #pragma unroll
    for (int t = 0; t < 4; ++t)
        sm[ty + 8*t][tx] = Z[(size_t)(i0 + ty + 8*t) * D_ + d0 + tx];
    __syncthreads();
    __nv_bfloat16* Yh = g_Zth + (size_t)b * D_ * NK_;
    __nv_bfloat16* Yl = g_Ztl + (size_t)b * D_ * NK_;
    #pragma unroll
    for (int t = 0; t < 4; ++t) {
        int d = d0 + ty + 8*t, i = i0 + tx;
        float x = sm[tx][ty + 8*t];
        __nv_bfloat16 hi = __float2bfloat16(x);
        __nv_bfloat16 lo = __float2bfloat16(x - __bfloat162float(hi));
        Yh[(size_t)d * NK_ + i] = hi;
        Yl[(size_t)d * NK_ + i] = lo;
    }
}

// ============ fused W-producer + out-GEMM ============
// out[k,d] = sum_i W[i,k]·Z[i,d] + lin_b[d]; W made in smem from g_St, m, si.
// block: k-tile 256 x d-tile 128; 16 warps (4 k x 4 d); 3 passes per i-tile.
#define WPITCH 272
__global__ __launch_bounds__(512, 1)
void out_fused(float* __restrict__ out, const float* __restrict__ lin_b)
{
    extern __shared__ __align__(16) char DS[];
    char* WH = DS;                 // 256 x 272
    char* WL = DS + 69632;         // 256 x 272
    char* ZH = DS + 139264;        // 128 x 272
    char* ZL = DS + 174080;        // 128 x 272
    int tid = threadIdx.x, wid = tid >> 5, lane = tid & 31;
    int b = blockIdx.z;
    int k0 = blockIdx.x * 256, d0 = blockIdx.y * 128;
    int wm = wid & 3, wn = wid >> 2;
    const float* St = g_St + (size_t)b * NQ_ * NK_;
    const float* mV = g_m  + b * NK_;
    const float* iV = g_si + b * NK_;
    const __nv_bfloat16* Zh = g_Zth + (size_t)b * D_ * NK_;
    const __nv_bfloat16* Zl = g_Ztl + (size_t)b * D_ * NK_;
    float acc[4][4][4] = {};

    for (int it = 0; it < 16; ++it) {
        int i0 = it * 128;
        // Z tiles via cp.async
        #pragma unroll
        for (int c = 0; c < 4; ++c) {
            int ch = tid + c * 512;
            int r = ch >> 4, q = ch & 15;
            CP16(smem_u32(ZH + r * WPITCH + q * 16), Zh + (size_t)(d0 + r) * NK_ + i0 + q * 8);
            CP16(smem_u32(ZL + r * WPITCH + q * 16), Zl + (size_t)(d0 + r) * NK_ + i0 + q * 8);
        }
        CP_COMMIT;
        // produce W tiles (256 rows of k, 128 cols of i)
        float4 m4 = *(const float4*)(mV + i0 + lane * 4);
        float4 v4 = *(const float4*)(iV + i0 + lane * 4);
        #pragma unroll 4
        for (int rr = 0; rr < 16; ++rr) {
            int r = wid + rr * 16;
            float4 s4 = *(const float4*)(St + (size_t)(k0 + r) * NK_ + i0 + lane * 4);
            float w0 = __expf(s4.x - m4.x) * v4.x;
            float w1 = __expf(s4.y - m4.y) * v4.y;
            float w2 = __expf(s4.z - m4.z) * v4.z;
            float w3 = __expf(s4.w - m4.w) * v4.w;
            __nv_bfloat16 h0 = __float2bfloat16(w0), h1 = __float2bfloat16(w1);
            __nv_bfloat16 h2 = __float2bfloat16(w2), h3 = __float2bfloat16(w3);
            __nv_bfloat16 l0 = __float2bfloat16(w0 - __bfloat162float(h0));
            __nv_bfloat16 l1 = __float2bfloat16(w1 - __bfloat162float(h1));
            __nv_bfloat16 l2 = __float2bfloat16(w2 - __bfloat162float(h2));
            __nv_bfloat16 l3 = __float2bfloat16(w3 - __bfloat162float(h3));
            __nv_bfloat162* ph = (__nv_bfloat162*)(WH + r * WPITCH + lane * 8);
            __nv_bfloat162 p0; p0.x = h0; p0.y = h1;
            __nv_bfloat162 p1; p1.x = h2; p1.y = h3;
            ph[0] = p0; ph[1] = p1;
            __nv_bfloat162* pl = (__nv_bfloat162*)(WL + r * WPITCH + lane * 8);
            __nv_bfloat162 q0; q0.x = l0; q0.y = l1;
            __nv_bfloat162 q1; q1.x = l2; q1.y = l3;
            pl[0] = q0; pl[1] = q1;
        }
        CP_WAIT0;
        __syncthreads();
        // 3 passes: (WH,ZH), (WL,ZH), (WH,ZL)
        #pragma unroll
        for (int pass = 0; pass < 3; ++pass) {
            char* Ab = (pass == 1) ? WL : WH;
            char* Bb = (pass == 2) ? ZL : ZH;
            #pragma unroll
            for (int ks = 0; ks < 8; ++ks) {
                uint32_t a[4][4], bb[4][2];
                #pragma unroll
                for (int t = 0; t < 4; ++t)
                    ldm_x4(a[t], smem_u32(Ab + (wm*64 + t*16 + (lane & 15)) * WPITCH
                                          + ks * 32 + ((lane >> 4) << 4)));
                #pragma unroll
                for (int u2 = 0; u2 < 2; ++u2) {
                    uint32_t row = wn*32 + u2*16 + ((lane >> 4) << 3) + (lane & 7);
                    uint32_t koff = ks * 32 + (((lane >> 3) & 1) << 4);
                    uint32_t r4[4];
                    ldm_x4(r4, smem_u32(Bb + row * WPITCH + koff));
                    bb[u2*2][0] = r4[0]; bb[u2*2][1] = r4[1];
                    bb[u2*2+1][0] = r4[2]; bb[u2*2+1][1] = r4[3];
                }
                #pragma unroll
                for (int t = 0; t < 4; ++t)
                    #pragma unroll
                    for (int u = 0; u < 4; ++u)
                        mma16816(acc[t][u], a[t], bb[u]);
            }
        }
        __syncthreads();
    }
    // epilogue: out[b][k][d] + lin_b[d]
    float* O = out + (size_t)b * NQ_ * D_;
    #pragma unroll
    for (int t = 0; t < 4; ++t) {
        int r0 = k0 + wm*64 + t*16 + (lane >> 2);
        #pragma unroll
        for (int u = 0; u < 4; ++u) {
            int cc = d0 + wn*32 + u*8 + (lane & 3)*2;
            float b0 = lin_b[cc], b1 = lin_b[cc+1];
            float2 v0 = {acc[t][u][0] + b0, acc[t][u][1] + b1};
            float2 v1 = {acc[t][u][2] + b0, acc[t][u][3] + b1};
            *(float2*)&O[(size_t)r0 * D_ + cc]       = v0;
            *(float2*)&O[(size_t)(r0 + 8) * D_ + cc] = v1;
        }
    }
}

// ======================= launcher =======================
extern "C" void kernel_launch(void* const* d_in, const int* in_sizes, int n_in,
                              void* d_out, int out_size) {
    const float* KEY   = (const float*)d_in[0];
    const float* VALUE = (const float*)d_in[1];
    const float* QUERY = (const float*)d_in[2];
    const float* Wk_w  = (const float*)d_in[3];
    const float* Wk_b  = (const float*)d_in[4];
    const float* Wq_w  = (const float*)d_in[5];
    /* Wq_b (d_in[6]) cancels exactly under softmax over k */
    const float* Wv_w  = (const float*)d_in[7];
    const float* Wv_b  = (const float*)d_in[8];
    const float* lin_w = (const float*)d_in[9];
    const float* lin_b = (const float*)d_in[10];
    float* out = (float*)d_out;

    __nv_bfloat16 *pK2, *pV2, *pQ2, *pP2, *pGt2, *pM22;
    float *pZ, *pGt, *pM2, *pcv;
    cudaGetSymbolAddress((void**)&pK2,  g_K2);
    cudaGetSymbolAddress((void**)&pV2,  g_V2);
    cudaGetSymbolAddress((void**)&pQ2,  g_Q2);
    cudaGetSymbolAddress((void**)&pP2,  g_P2);
    cudaGetSymbolAddress((void**)&pGt2, g_Gt2);
    cudaGetSymbolAddress((void**)&pM22, g_M22);
    cudaGetSymbolAddress((void**)&pZ,   g_Z);
    cudaGetSymbolAddress((void**)&pGt,  g_Gt);
    cudaGetSymbolAddress((void**)&pM2,  g_M2);
    cudaGetSymbolAddress((void**)&pcv,  g_cv);

    const size_t sRow = (size_t)NK_ * KS3;
    const size_t sZ   = (size_t)NK_ * D_;

    const int OUT_SMEM = 208896;
    cudaFuncSetAttribute(out_fused, cudaFuncAttributeMaxDynamicSharedMemorySize, OUT_SMEM);

    // precompute
    transpose_lin<<<H_ * D_ / 256, 256>>>(lin_w);
    vec_pre<<<2, 256>>>(Wk_b, Wq_w, lin_w, Wv_b);
    small_gemm_tn<<<dim3(8, 8, 2), 256>>>(Wq_w, Wk_w, Wv_w);
    qdotg<<<(B_ * NQ_) / 8, 256>>>(QUERY);

    // splits
    split_rows<true ><<<(B_ * NK_ * D_) / 256, 256>>>(KEY,   pK2);
    split_rows<true ><<<(B_ * NK_ * D_) / 256, 256>>>(VALUE, pV2);
    split_rows<false><<<(B_ * NQ_ * D_) / 256, 256>>>(QUERY, pQ2);
    split_rows<false><<<(D_ * D_) / 256, 256>>>(pGt, pGt2);
    split_rows<false><<<(D_ * D_) / 256, 256>>>(pM2, pM22);

    // P2 = split(KEY @ Gt^T)   [A-form]
    mma_gemm<2><<<dim3(16, 2, B_), 256>>>(pK2, pGt2, pP2, nullptr,
                                          KS3, sRow, 0, sRow, 0);
    // Z = VALUE @ M2^T + cv    fp32 [i,d]
    mma_gemm<0><<<dim3(16, 2, B_), 256>>>(pV2, pM22, pZ, pcv,
                                          KS3, sRow, 0, sZ, D_);
    // S'^T + tile stats
    sgemm_stats<<<dim3(16, 16, B_), 256>>>();
    stats_combine<<<dim3(8, B_), 256>>>();
    transpose_split_z<<<dim3(64, 8, B_), dim3(32, 8)>>>();
    // fused softmax-weights + out GEMM
    out_fused<<<dim3(8, 2, B_), 512, OUT_SMEM>>>(out, lin_b);
}